// round 15
// baseline (speedup 1.0000x reference)
#include <cuda_runtime.h>
#include <math.h>

#define NH 8
#define SEQ 32
#define DK 8
#define DM 64
#define PI_F 3.14159265358979323846f
#define W_MUL 0.6324555320336759f  // sqrt(2/5)

#define XPAD 68          // padded x/W1 stage row (floats); rows 16B-aligned

// packed f32x2 helpers (sm_103a FFMA2 path — only reachable via PTX)
#define FMA2(d, a, b, c) \
    asm("fma.rn.f32x2 %0, %1, %2, %3;" : "=l"(d) : "l"(a), "l"(b), "l"(c))
#define PACK2(out, lo, hi) \
    asm("mov.b64 %0, {%1, %2};" : "=l"(out) : "f"(lo), "f"(hi))
#define UNPACK2(lo, hi, in) \
    asm("mov.b64 {%0, %1}, %2;" : "=f"(lo), "=f"(hi) : "l"(in))

__device__ __forceinline__ float2 cmul(float2 a, float2 b) {
    return make_float2(fmaf(a.x, b.x, -a.y * b.y), fmaf(a.x, b.y, a.y * b.x));
}
// a * conj(b)
__device__ __forceinline__ float2 cmulc(float2 a, float2 b) {
    return make_float2(fmaf(a.x, b.x, a.y * b.y), fmaf(a.y, b.x, -a.x * b.y));
}
__device__ __forceinline__ float2 cadd(float2 a, float2 b) {
    return make_float2(a.x + b.x, a.y + b.y);
}
// acc += a*b
__device__ __forceinline__ void cmac(float2& acc, float2 a, float2 b) {
    acc.x = fmaf(a.x, b.x, fmaf(-a.y, b.y, acc.x));
    acc.y = fmaf(a.x, b.y, fmaf( a.y, b.x, acc.y));
}

// flat-64 gather permutation: P(m) = r(m>>3)*8 + r(m&7), r(a)=a^(a>>1). order 4.
__device__ __forceinline__ int Pmap(int m) {
    int a = m >> 3, c = m & 7;
    int ra = (a ^ (a >> 1)) & 7;
    int rc = (c ^ (c >> 1)) & 7;
    return ra * 8 + rc;
}

// apply 3-qubit kron unitary to REAL vector psi[8] (stage 1 specialized)
__device__ __forceinline__ void apply_u3_real(const float2 (*u)[4],
                                              const float* psi, float2* v) {
    {
        float2 u0 = u[0][0], u1 = u[0][1], u2 = u[0][2], u3 = u[0][3];
#pragma unroll
        for (int k = 0; k < 4; k++) {
            float a = psi[k], b = psi[k | 4];
            v[k]     = make_float2(fmaf(u0.x, a, u1.x * b), fmaf(u0.y, a, u1.y * b));
            v[k | 4] = make_float2(fmaf(u2.x, a, u3.x * b), fmaf(u2.y, a, u3.y * b));
        }
    }
#pragma unroll
    for (int q = 1; q < 3; q++) {
        int p = 2 - q;
        float2 u0 = u[q][0], u1 = u[q][1], u2 = u[q][2], u3 = u[q][3];
#pragma unroll
        for (int k = 0; k < 8; k++) {
            if ((k >> p) & 1) continue;
            int k1 = k | (1 << p);
            float2 v0 = v[k], v1 = v[k1];
            v[k]  = cadd(cmul(u0, v0), cmul(u1, v1));
            v[k1] = cadd(cmul(u2, v0), cmul(u3, v1));
        }
    }
}

__device__ __forceinline__ float2 shfl2(float2 v, int m) {
    return make_float2(__shfl_xor_sync(0xffffffffu, v.x, m),
                       __shfl_xor_sync(0xffffffffu, v.y, m));
}

// grid = 32 (block = sequence row i), block = 256 (warp w = head h)
__global__ void __launch_bounds__(256)
qfused(const float* __restrict__ x,     // (32,64)
       const float* __restrict__ pqc,   // (8,3,9)
       const float* __restrict__ W1,    // (8,64)
       const float* __restrict__ b1,    // (8,)
       const float* __restrict__ W2,    // (64,64)
       const float* __restrict__ b2,    // (64,)
       float* __restrict__ out)         // (1,32,64)
{
    const int i = blockIdx.x;        // sequence row
    const int t = threadIdx.x;       // 0..255
    const int w = t >> 5;            // warp = head
    const int l = t & 31;

    __shared__ float  s_xs [SEQ][XPAD];       // staged x
    __shared__ float  s_ws [DK][XPAD];        // staged W1
    __shared__ float  s_psi[SEQ][9];
    __shared__ float2 s_u[NH][3][3][4];       // per-head unitaries
    __shared__ float4 s_M[NH][3];             // Ma, Mc, Mb: (M00, M11, Re01, Im01)
    __shared__ float2 s_V[NH][SEQ][4];        // per (head,j): v00,v01,v10,v11
    __shared__ float2 s_chi0[NH][8];
    __shared__ float  s_part[NH][65];

    // ---- Prefetch W2 rows + b2 (latency hidden under prep) ----
    float4 wa0, wa1, wb0, wb1;
    {
        const float4* w2a = (const float4*)(W2 + l * DM + w * DK);
        const float4* w2b = (const float4*)(W2 + (l + 32) * DM + w * DK);
        wa0 = w2a[0]; wa1 = w2a[1];
        wb0 = w2b[0]; wb1 = w2b[1];
    }
    float bias = (t < DM) ? b2[t] : 0.f;

    // ---- Phase 0: stage x/W1 + per-head unitaries + sign-form M's ----
    {
        const float4* xs = (const float4*)x;
#pragma unroll
        for (int k = 0; k < 2; k++) {
            int q = t + 256 * k;          // 0..511
            int s = q >> 4, j = q & 15;
            *(float4*)&s_xs[s][4 * j] = xs[q];
        }
        if (t < 128) {
            int c = t >> 4, j = t & 15;
            *(float4*)&s_ws[c][4 * j] = ((const float4*)W1)[t];
        }
    }
    if (l < 9) {                          // warp w builds head w's 9 unitaries
        int g = l / 3, q = l % 3;
        const float* ap = pqc + w * 27 + g * 9 + q * 3;
        float a0 = ap[0] * W_MUL, a1 = ap[1] * W_MUL, a2 = ap[2] * W_MUL;
        float sx, cx, sy, cy, sz, cz;
        __sincosf(0.5f * a0, &sx, &cx);
        __sincosf(0.5f * a1, &sy, &cy);
        __sincosf(0.5f * a2, &sz, &cz);
        float2 m00 = make_float2(cy * cx,   sy * sx);
        float2 m01 = make_float2(-sy * cx, -cy * sx);
        float2 m10 = make_float2(sy * cx,  -cy * sx);
        float2 m11 = make_float2(cy * cx,  -sy * sx);
        float2 e0 = make_float2(cz, -sz);
        float2 e1 = make_float2(cz,  sz);
        s_u[w][g][q][0] = cmul(e0, m00);
        s_u[w][g][q][1] = cmul(e0, m01);
        s_u[w][g][q][2] = cmul(e1, m10);
        s_u[w][g][q][3] = cmul(e1, m11);
        // M = u^dagger Z u (Rz phases cancel row-wise)
        if (l == 0 || l == 2 || l == 4) {
            int idx = (l == 0) ? 0 : (l == 2) ? 1 : 2;
            float M00 = fmaf(m00.x, m00.x, m00.y * m00.y)
                      - fmaf(m10.x, m10.x, m10.y * m10.y);
            float M11 = fmaf(m01.x, m01.x, m01.y * m01.y)
                      - fmaf(m11.x, m11.x, m11.y * m11.y);
            float2 t1 = cmulc(m01, m00);
            float2 t2 = cmulc(m11, m10);
            s_M[w][idx] = make_float4(M00, M11, t1.x - t2.x, t1.y - t2.y);
        }
    }
    __syncthreads();

    // ---- Phase 1: xq + normalize fused, packed f32x2 dot product ----
    {
        const int c = t & 7;
        const int s = t >> 3;             // 0..31
        const ulonglong2* wr = (const ulonglong2*)&s_ws[c][0];
        const ulonglong2* xr = (const ulonglong2*)&s_xs[s][0];
        unsigned long long acc0, acc1;
        float bc = b1[c];
        PACK2(acc0, bc, 0.0f);
        PACK2(acc1, 0.0f, 0.0f);
#pragma unroll
        for (int j = 0; j < 8; j++) {
            ulonglong2 wv = wr[j];
            ulonglong2 xv = xr[j];
            FMA2(acc0, xv.x, wv.x, acc0);
            FMA2(acc1, xv.y, wv.y, acc1);
        }
        float u0f, u1f, u2f, u3f;
        UNPACK2(u0f, u1f, acc0);
        UNPACK2(u2f, u3f, acc1);
        float a = (u0f + u1f) + (u2f + u3f);
        float sq = a * a;
#pragma unroll
        for (int d = 1; d < 8; d <<= 1)
            sq += __shfl_xor_sync(0xffffffffu, sq, d);
        s_psi[s][c] = a * rsqrtf(sq);
    }
    __syncthreads();

    // ============ everything below is warp-local (head h = w) ============

    // ---- Phase 3: K_l and Q via Kronecker quadratic forms; pv butterfly ----
    float ph;
    float2 pv[8];
    {
        float psl[8];
#pragma unroll
        for (int e = 0; e < 8; e++) psl[e] = s_psi[l][e];
        apply_u3_real(s_u[w][2], psl, pv);

        // K_l = psi_l^T (I (x) Mb (x) I) psi_l
        float4 Mb = s_M[w][2];
        float s0 = fmaf(psl[0], psl[0], fmaf(psl[1], psl[1],
                   fmaf(psl[4], psl[4], psl[5] * psl[5])));
        float s1 = fmaf(psl[2], psl[2], fmaf(psl[3], psl[3],
                   fmaf(psl[6], psl[6], psl[7] * psl[7])));
        float sx = fmaf(psl[0], psl[2], fmaf(psl[1], psl[3],
                   fmaf(psl[4], psl[6], psl[5] * psl[7])));
        float K = fmaf(Mb.x, s0, fmaf(Mb.y, s1, 2.f * Mb.z * sx));

        // Q = psi_i^T (Ma (x) I (x) Mc) psi_i
        float qv[8];
#pragma unroll
        for (int e = 0; e < 8; e++) qv[e] = s_psi[i][e];    // broadcast
        float S00 = fmaf(qv[0], qv[0], qv[2] * qv[2]);
        float S11 = fmaf(qv[1], qv[1], qv[3] * qv[3]);
        float S22 = fmaf(qv[4], qv[4], qv[6] * qv[6]);
        float S33 = fmaf(qv[5], qv[5], qv[7] * qv[7]);
        float S01 = fmaf(qv[0], qv[1], qv[2] * qv[3]);
        float S23 = fmaf(qv[4], qv[5], qv[6] * qv[7]);
        float S02 = fmaf(qv[0], qv[4], qv[2] * qv[6]);
        float S13 = fmaf(qv[1], qv[5], qv[3] * qv[7]);
        float S03 = fmaf(qv[0], qv[5], qv[2] * qv[7]);
        float S12 = fmaf(qv[1], qv[4], qv[3] * qv[6]);
        float4 Ma = s_M[w][0], Mc = s_M[w][1];
        float Q = Ma.x * fmaf(Mc.x, S00, Mc.y * S11)
                + Ma.y * fmaf(Mc.x, S22, Mc.y * S33)
                + 2.f * ( fmaf(Ma.x * Mc.z, S01, Ma.y * Mc.z * S23)
                        + fmaf(Ma.z * Mc.x, S02, Ma.z * Mc.y * S13)
                        + fmaf(Ma.z * Mc.z - Ma.w * Mc.w, S03,
                               (Ma.z * Mc.z + Ma.w * Mc.w) * S12) );

        ph = PI_F * Q * K;
    }

    // ---- Phase 5: chi_l = Uw(phi_l) pv_l;  V row ----
    // n0 + n1 = |chi|^2 = 1 (unitary, |pv| = 1) -> n1 = 1 - n0
    {
        float s4, c4;
        __sincosf(0.25f * ph, &s4, &c4);
        float cc2 = c4 * c4, ss2 = s4 * s4, cs2 = c4 * s4;
        float sh = 2.f * cs2;             // sin(ph/2)
        float ch = cc2 - ss2;             // cos(ph/2)
        float2 e0 = make_float2(ch, -sh);
        float2 e1 = make_float2(ch,  sh);
        float2 u0 = cmul(e0, make_float2(cc2,  ss2));
        float2 u1 = cmul(e0, make_float2(-cs2, -cs2));
        float2 u2 = cmul(e1, make_float2(cs2,  -cs2));
        float2 u3 = cmul(e1, make_float2(cc2,  -ss2));

        float2 v[8];
#pragma unroll
        for (int e = 0; e < 8; e++) v[e] = pv[e];
#pragma unroll
        for (int q = 0; q < 3; q++) {
            int p = 2 - q;
#pragma unroll
            for (int k = 0; k < 8; k++) {
                if ((k >> p) & 1) continue;
                int k1 = k | (1 << p);
                float2 v0 = v[k], v1 = v[k1];
                v[k]  = cadd(cmul(u0, v0), cmul(u1, v1));
                v[k1] = cadd(cmul(u2, v0), cmul(u3, v1));
            }
        }
        float n0 = fmaf(v[0].x, v[0].x, v[0].y * v[0].y)
                 + fmaf(v[3].x, v[3].x, v[3].y * v[3].y)
                 + fmaf(v[5].x, v[5].x, v[5].y * v[5].y)
                 + fmaf(v[6].x, v[6].x, v[6].y * v[6].y);
        float n1 = 1.0f - n0;             // unitarity
        float2 V01 = make_float2(0.f, 0.f);
        V01 = cadd(V01, cmulc(v[0], v[4]));
        V01 = cadd(V01, cmulc(v[3], v[7]));
        V01 = cadd(V01, cmulc(v[5], v[1]));
        V01 = cadd(V01, cmulc(v[6], v[2]));
        s_V[w][l][0] = make_float2(n0, 0.f);
        s_V[w][l][1] = V01;
        s_V[w][l][2] = make_float2(n1, 0.f);
        s_V[w][l][3] = make_float2(V01.x, -V01.y);   // V11 = conj(V01)
        if (l == 0) {
#pragma unroll
            for (int e = 0; e < 8; e++) s_chi0[w][e] = v[e];
        }
    }
    __syncwarp();

    // ---- Phase 6: drifting-coordinate register scan ----
    // slot0 sel table only; slot1 sel = slot0 sel ^ {0,3,3,0}[k]
    int selA0[4];
    {
        int m = l;
        int p1 = Pmap(m), p2 = Pmap(p1), p3 = Pmap(p2);
        selA0[0] = (((m  >> 3) & 1) << 1) | ((((m  >> 3) ^ m ) & 1));
        selA0[1] = (((p3 >> 3) & 1) << 1) | ((((p3 >> 3) ^ p3) & 1));
        selA0[2] = (((p2 >> 3) & 1) << 1) | ((((p2 >> 3) ^ p2) & 1));
        selA0[3] = (((p1 >> 3) & 1) << 1) | ((((p1 >> 3) ^ p1) & 1));
    }
    const int dmarr[4] = {4, 22, 13, 31};

    float2 r0, r1;
    {
        float2 ca  = s_chi0[w][l >> 3];
        float2 ca1 = s_chi0[w][4 + (l >> 3)];
        float2 cc  = s_chi0[w][l & 7];
        r0 = cmulc(ca, cc);
        r1 = cmulc(ca1, cc);
    }

#pragma unroll
    for (int j = 1; j < SEQ; j++) {
        const int k = j & 3;
        const float2* vj = &s_V[w][j][0];

        float2 p0 = shfl2(r1, dmarr[k]);
        float2 p1 = shfl2(r0, dmarr[k]);

        float2 VA0 = vj[selA0[k]];
        float2 VB0 = vj[selA0[k] ^ 2];

        float2 n0 = cmul(r0, VA0); cmac(n0, p0, VB0);
        float2 n1;
        if (k == 0 || k == 3) {
            n1 = cmul(r1, VA0); cmac(n1, p1, VB0);
        } else {
            float2 VA1 = vj[selA0[k] ^ 3];
            float2 VB1 = vj[selA0[k] ^ 1];
            n1 = cmul(r1, VA1); cmac(n1, p1, VB1);
        }
        r0 = n0; r1 = n1;
    }

    // ---- diagonal extraction via fixed-source shuffles ----
    float zr[8];
    zr[0] = __shfl_sync(0xffffffffu, r0.x, 0);
    zr[1] = __shfl_sync(0xffffffffu, r0.x, 9);
    zr[2] = __shfl_sync(0xffffffffu, r0.x, 27);
    zr[3] = __shfl_sync(0xffffffffu, r0.x, 18);
    zr[4] = __shfl_sync(0xffffffffu, r1.x, 31);
    zr[5] = __shfl_sync(0xffffffffu, r1.x, 22);
    zr[6] = __shfl_sync(0xffffffffu, r1.x, 4);
    zr[7] = __shfl_sync(0xffffffffu, r1.x, 13);

    // ---- Phase 7: per-head output partials (W2 already in registers) ----
    {
        float p0 = zr[0] * wa0.x + zr[1] * wa0.y + zr[2] * wa0.z + zr[3] * wa0.w
                 + zr[4] * wa1.x + zr[5] * wa1.y + zr[6] * wa1.z + zr[7] * wa1.w;
        float p1 = zr[0] * wb0.x + zr[1] * wb0.y + zr[2] * wb0.z + zr[3] * wb0.w
                 + zr[4] * wb1.x + zr[5] * wb1.y + zr[6] * wb1.z + zr[7] * wb1.w;
        s_part[w][l]      = p0;
        s_part[w][l + 32] = p1;
    }
    __syncthreads();

    // ---- Phase 8: cross-head reduction, write out row i ----
    if (t < DM) {
        float acc = bias;
#pragma unroll
        for (int hh = 0; hh < NH; hh++) acc += s_part[hh][t];
        out[i * DM + t] = acc;
    }
}

extern "C" void kernel_launch(void* const* d_in, const int* in_sizes, int n_in,
                              void* d_out, int out_size) {
    const float* x    = (const float*)d_in[0];
    const float* pqc  = (const float*)d_in[1];
    const float* W1   = (const float*)d_in[2];
    const float* b1   = (const float*)d_in[3];
    const float* W2   = (const float*)d_in[4];
    const float* b2   = (const float*)d_in[5];
    float* out = (float*)d_out;

    qfused<<<SEQ, 256>>>(x, pqc, W1, b1, W2, b2, out);
}

// round 16
// speedup vs baseline: 1.0332x; 1.0332x over previous
#include <cuda_runtime.h>
#include <math.h>

#define NH 8
#define SEQ 32
#define DK 8
#define DM 64
#define PI_F 3.14159265358979323846f
#define W_MUL 0.6324555320336759f  // sqrt(2/5)

#define XPAD 68          // padded x/W1 stage row (floats); rows 16B-aligned

// packed f32x2 helpers (sm_103a FFMA2 path — only reachable via PTX)
#define FMA2(d, a, b, c) \
    asm("fma.rn.f32x2 %0, %1, %2, %3;" : "=l"(d) : "l"(a), "l"(b), "l"(c))
#define PACK2(out, lo, hi) \
    asm("mov.b64 %0, {%1, %2};" : "=l"(out) : "f"(lo), "f"(hi))
#define UNPACK2(lo, hi, in) \
    asm("mov.b64 {%0, %1}, %2;" : "=f"(lo), "=f"(hi) : "l"(in))

__device__ __forceinline__ float2 cmul(float2 a, float2 b) {
    return make_float2(fmaf(a.x, b.x, -a.y * b.y), fmaf(a.x, b.y, a.y * b.x));
}
// a * conj(b)
__device__ __forceinline__ float2 cmulc(float2 a, float2 b) {
    return make_float2(fmaf(a.x, b.x, a.y * b.y), fmaf(a.y, b.x, -a.x * b.y));
}
__device__ __forceinline__ float2 cadd(float2 a, float2 b) {
    return make_float2(a.x + b.x, a.y + b.y);
}
// acc += a*b
__device__ __forceinline__ void cmac(float2& acc, float2 a, float2 b) {
    acc.x = fmaf(a.x, b.x, fmaf(-a.y, b.y, acc.x));
    acc.y = fmaf(a.x, b.y, fmaf( a.y, b.x, acc.y));
}

// flat-64 gather permutation: P(m) = r(m>>3)*8 + r(m&7), r(a)=a^(a>>1). order 4.
__device__ __forceinline__ int Pmap(int m) {
    int a = m >> 3, c = m & 7;
    int ra = (a ^ (a >> 1)) & 7;
    int rc = (c ^ (c >> 1)) & 7;
    return ra * 8 + rc;
}

// apply 3-qubit kron unitary (per-qubit factors f[q]) to REAL vector psi[8]
__device__ __forceinline__ void apply_u3_real(const float2 (*u)[4],
                                              const float* psi, float2* v) {
    {
        float2 u0 = u[0][0], u1 = u[0][1], u2 = u[0][2], u3 = u[0][3];
#pragma unroll
        for (int k = 0; k < 4; k++) {
            float a = psi[k], b = psi[k | 4];
            v[k]     = make_float2(fmaf(u0.x, a, u1.x * b), fmaf(u0.y, a, u1.y * b));
            v[k | 4] = make_float2(fmaf(u2.x, a, u3.x * b), fmaf(u2.y, a, u3.y * b));
        }
    }
#pragma unroll
    for (int q = 1; q < 3; q++) {
        int p = 2 - q;
        float2 u0 = u[q][0], u1 = u[q][1], u2 = u[q][2], u3 = u[q][3];
#pragma unroll
        for (int k = 0; k < 8; k++) {
            if ((k >> p) & 1) continue;
            int k1 = k | (1 << p);
            float2 v0 = v[k], v1 = v[k1];
            v[k]  = cadd(cmul(u0, v0), cmul(u1, v1));
            v[k1] = cadd(cmul(u2, v0), cmul(u3, v1));
        }
    }
}

__device__ __forceinline__ float2 shfl2(float2 v, int m) {
    return make_float2(__shfl_xor_sync(0xffffffffu, v.x, m),
                       __shfl_xor_sync(0xffffffffu, v.y, m));
}

// grid = 32 (block = sequence row i), block = 256 (warp w = head h)
__global__ void __launch_bounds__(256)
qfused(const float* __restrict__ x,     // (32,64)
       const float* __restrict__ pqc,   // (8,3,9)
       const float* __restrict__ W1,    // (8,64)
       const float* __restrict__ b1,    // (8,)
       const float* __restrict__ W2,    // (64,64)
       const float* __restrict__ b2,    // (64,)
       float* __restrict__ out)         // (1,32,64)
{
    const int i = blockIdx.x;        // sequence row
    const int t = threadIdx.x;       // 0..255
    const int w = t >> 5;            // warp = head
    const int l = t & 31;

    __shared__ float  s_xs [SEQ][XPAD];       // staged x
    __shared__ float  s_ws [DK][XPAD];        // staged W1
    __shared__ float  s_psi[SEQ][9];
    __shared__ float2 s_u[NH][3][3][4];       // per-head unitaries
    __shared__ float4 s_M[NH][3];             // Ma, Mc, Mb: (M00, M11, Re01, Im01)
    __shared__ float2 s_V[NH][SEQ][4];        // per (head,j): v00,v01,v10,v11
    __shared__ float2 s_chi0[NH][8];
    __shared__ float  s_part[NH][65];

    // ---- Prefetch W2 rows + b2 (latency hidden under prep) ----
    float4 wa0, wa1, wb0, wb1;
    {
        const float4* w2a = (const float4*)(W2 + l * DM + w * DK);
        const float4* w2b = (const float4*)(W2 + (l + 32) * DM + w * DK);
        wa0 = w2a[0]; wa1 = w2a[1];
        wb0 = w2b[0]; wb1 = w2b[1];
    }
    float bias = (t < DM) ? b2[t] : 0.f;

    // ---- Phase 0: stage x/W1 + per-head unitaries + sign-form M's ----
    {
        const float4* xs = (const float4*)x;
#pragma unroll
        for (int k = 0; k < 2; k++) {
            int q = t + 256 * k;          // 0..511
            int s = q >> 4, j = q & 15;
            *(float4*)&s_xs[s][4 * j] = xs[q];
        }
        if (t < 128) {
            int c = t >> 4, j = t & 15;
            *(float4*)&s_ws[c][4 * j] = ((const float4*)W1)[t];
        }
    }
    if (l < 9) {                          // warp w builds head w's 9 unitaries
        int g = l / 3, q = l % 3;
        const float* ap = pqc + w * 27 + g * 9 + q * 3;
        float a0 = ap[0] * W_MUL, a1 = ap[1] * W_MUL, a2 = ap[2] * W_MUL;
        float sx, cx, sy, cy, sz, cz;
        __sincosf(0.5f * a0, &sx, &cx);
        __sincosf(0.5f * a1, &sy, &cy);
        __sincosf(0.5f * a2, &sz, &cz);
        float2 m00 = make_float2(cy * cx,   sy * sx);
        float2 m01 = make_float2(-sy * cx, -cy * sx);
        float2 m10 = make_float2(sy * cx,  -cy * sx);
        float2 m11 = make_float2(cy * cx,  -sy * sx);
        float2 e0 = make_float2(cz, -sz);
        float2 e1 = make_float2(cz,  sz);
        s_u[w][g][q][0] = cmul(e0, m00);
        s_u[w][g][q][1] = cmul(e0, m01);
        s_u[w][g][q][2] = cmul(e1, m10);
        s_u[w][g][q][3] = cmul(e1, m11);
        // M = u^dagger Z u (Rz phases cancel row-wise)
        if (l == 0 || l == 2 || l == 4) {
            int idx = (l == 0) ? 0 : (l == 2) ? 1 : 2;
            float M00 = fmaf(m00.x, m00.x, m00.y * m00.y)
                      - fmaf(m10.x, m10.x, m10.y * m10.y);
            float M11 = fmaf(m01.x, m01.x, m01.y * m01.y)
                      - fmaf(m11.x, m11.x, m11.y * m11.y);
            float2 t1 = cmulc(m01, m00);
            float2 t2 = cmulc(m11, m10);
            s_M[w][idx] = make_float4(M00, M11, t1.x - t2.x, t1.y - t2.y);
        }
    }
    __syncthreads();

    // ---- Phase 1: xq + normalize fused, packed f32x2 dot product ----
    {
        const int c = t & 7;
        const int s = t >> 3;             // 0..31
        const ulonglong2* wr = (const ulonglong2*)&s_ws[c][0];
        const ulonglong2* xr = (const ulonglong2*)&s_xs[s][0];
        unsigned long long acc0, acc1;
        float bc = b1[c];
        PACK2(acc0, bc, 0.0f);
        PACK2(acc1, 0.0f, 0.0f);
#pragma unroll
        for (int j = 0; j < 8; j++) {
            ulonglong2 wv = wr[j];
            ulonglong2 xv = xr[j];
            FMA2(acc0, xv.x, wv.x, acc0);
            FMA2(acc1, xv.y, wv.y, acc1);
        }
        float u0f, u1f, u2f, u3f;
        UNPACK2(u0f, u1f, acc0);
        UNPACK2(u2f, u3f, acc1);
        float a = (u0f + u1f) + (u2f + u3f);
        float sq = a * a;
#pragma unroll
        for (int d = 1; d < 8; d <<= 1)
            sq += __shfl_xor_sync(0xffffffffu, sq, d);
        s_psi[s][c] = a * rsqrtf(sq);
    }
    __syncthreads();

    // ============ everything below is warp-local (head h = w) ============

    // ---- Phase 3: K_l and Q via Kronecker quadratic forms (no butterfly) ----
    float ph;
    float psl[8];
    {
#pragma unroll
        for (int e = 0; e < 8; e++) psl[e] = s_psi[l][e];

        // K_l = psi_l^T (I (x) Mb (x) I) psi_l
        float4 Mb = s_M[w][2];
        float s0 = fmaf(psl[0], psl[0], fmaf(psl[1], psl[1],
                   fmaf(psl[4], psl[4], psl[5] * psl[5])));
        float s1 = fmaf(psl[2], psl[2], fmaf(psl[3], psl[3],
                   fmaf(psl[6], psl[6], psl[7] * psl[7])));
        float sx = fmaf(psl[0], psl[2], fmaf(psl[1], psl[3],
                   fmaf(psl[4], psl[6], psl[5] * psl[7])));
        float K = fmaf(Mb.x, s0, fmaf(Mb.y, s1, 2.f * Mb.z * sx));

        // Q = psi_i^T (Ma (x) I (x) Mc) psi_i
        float qv[8];
#pragma unroll
        for (int e = 0; e < 8; e++) qv[e] = s_psi[i][e];    // broadcast
        float S00 = fmaf(qv[0], qv[0], qv[2] * qv[2]);
        float S11 = fmaf(qv[1], qv[1], qv[3] * qv[3]);
        float S22 = fmaf(qv[4], qv[4], qv[6] * qv[6]);
        float S33 = fmaf(qv[5], qv[5], qv[7] * qv[7]);
        float S01 = fmaf(qv[0], qv[1], qv[2] * qv[3]);
        float S23 = fmaf(qv[4], qv[5], qv[6] * qv[7]);
        float S02 = fmaf(qv[0], qv[4], qv[2] * qv[6]);
        float S13 = fmaf(qv[1], qv[5], qv[3] * qv[7]);
        float S03 = fmaf(qv[0], qv[5], qv[2] * qv[7]);
        float S12 = fmaf(qv[1], qv[4], qv[3] * qv[6]);
        float4 Ma = s_M[w][0], Mc = s_M[w][1];
        float Q = Ma.x * fmaf(Mc.x, S00, Mc.y * S11)
                + Ma.y * fmaf(Mc.x, S22, Mc.y * S33)
                + 2.f * ( fmaf(Ma.x * Mc.z, S01, Ma.y * Mc.z * S23)
                        + fmaf(Ma.z * Mc.x, S02, Ma.z * Mc.y * S13)
                        + fmaf(Ma.z * Mc.z - Ma.w * Mc.w, S03,
                               (Ma.z * Mc.z + Ma.w * Mc.w) * S12) );

        ph = PI_F * Q * K;
    }

    // ---- Phase 5: chi_l = (uw u2a)(x)(uw u2b)(x)(uw u2c) psi_l (ONE butterfly) ----
    // n0 + n1 = |chi|^2 = 1 (unitary, |psi| = 1) -> n1 = 1 - n0
    {
        float s4, c4;
        __sincosf(0.25f * ph, &s4, &c4);
        float cc2 = c4 * c4, ss2 = s4 * s4, cs2 = c4 * s4;
        float sh = 2.f * cs2;             // sin(ph/2)
        float ch = cc2 - ss2;             // cos(ph/2)
        float2 e0 = make_float2(ch, -sh);
        float2 e1 = make_float2(ch,  sh);
        float2 uw0 = cmul(e0, make_float2(cc2,  ss2));
        float2 uw1 = cmul(e0, make_float2(-cs2, -cs2));
        float2 uw2 = cmul(e1, make_float2(cs2,  -cs2));
        float2 uw3 = cmul(e1, make_float2(cc2,  -ss2));

        // fused per-qubit factors f[q] = uw * u2[q]  (2x2 complex products)
        float2 f[3][4];
#pragma unroll
        for (int q = 0; q < 3; q++) {
            float2 a00 = s_u[w][2][q][0], a01 = s_u[w][2][q][1];
            float2 a10 = s_u[w][2][q][2], a11 = s_u[w][2][q][3];
            f[q][0] = cadd(cmul(uw0, a00), cmul(uw1, a10));
            f[q][1] = cadd(cmul(uw0, a01), cmul(uw1, a11));
            f[q][2] = cadd(cmul(uw2, a00), cmul(uw3, a10));
            f[q][3] = cadd(cmul(uw2, a01), cmul(uw3, a11));
        }

        float2 v[8];
        apply_u3_real(f, psl, v);

        float n0 = fmaf(v[0].x, v[0].x, v[0].y * v[0].y)
                 + fmaf(v[3].x, v[3].x, v[3].y * v[3].y)
                 + fmaf(v[5].x, v[5].x, v[5].y * v[5].y)
                 + fmaf(v[6].x, v[6].x, v[6].y * v[6].y);
        float n1 = 1.0f - n0;             // unitarity
        float2 V01 = make_float2(0.f, 0.f);
        V01 = cadd(V01, cmulc(v[0], v[4]));
        V01 = cadd(V01, cmulc(v[3], v[7]));
        V01 = cadd(V01, cmulc(v[5], v[1]));
        V01 = cadd(V01, cmulc(v[6], v[2]));
        s_V[w][l][0] = make_float2(n0, 0.f);
        s_V[w][l][1] = V01;
        s_V[w][l][2] = make_float2(n1, 0.f);
        s_V[w][l][3] = make_float2(V01.x, -V01.y);   // V11 = conj(V01)
        if (l == 0) {
#pragma unroll
            for (int e = 0; e < 8; e++) s_chi0[w][e] = v[e];
        }
    }
    __syncwarp();

    // ---- Phase 6: drifting-coordinate register scan ----
    // slot0 sel table only; slot1 sel = slot0 sel ^ {0,3,3,0}[k]
    int selA0[4];
    {
        int m = l;
        int p1 = Pmap(m), p2 = Pmap(p1), p3 = Pmap(p2);
        selA0[0] = (((m  >> 3) & 1) << 1) | ((((m  >> 3) ^ m ) & 1));
        selA0[1] = (((p3 >> 3) & 1) << 1) | ((((p3 >> 3) ^ p3) & 1));
        selA0[2] = (((p2 >> 3) & 1) << 1) | ((((p2 >> 3) ^ p2) & 1));
        selA0[3] = (((p1 >> 3) & 1) << 1) | ((((p1 >> 3) ^ p1) & 1));
    }
    const int dmarr[4] = {4, 22, 13, 31};

    float2 r0, r1;
    {
        float2 ca  = s_chi0[w][l >> 3];
        float2 ca1 = s_chi0[w][4 + (l >> 3)];
        float2 cc  = s_chi0[w][l & 7];
        r0 = cmulc(ca, cc);
        r1 = cmulc(ca1, cc);
    }

#pragma unroll
    for (int j = 1; j < SEQ; j++) {
        const int k = j & 3;
        const float2* vj = &s_V[w][j][0];

        float2 p0 = shfl2(r1, dmarr[k]);
        float2 p1 = shfl2(r0, dmarr[k]);

        float2 VA0 = vj[selA0[k]];
        float2 VB0 = vj[selA0[k] ^ 2];

        float2 n0 = cmul(r0, VA0); cmac(n0, p0, VB0);
        float2 n1;
        if (k == 0 || k == 3) {
            n1 = cmul(r1, VA0); cmac(n1, p1, VB0);
        } else {
            float2 VA1 = vj[selA0[k] ^ 3];
            float2 VB1 = vj[selA0[k] ^ 1];
            n1 = cmul(r1, VA1); cmac(n1, p1, VB1);
        }
        r0 = n0; r1 = n1;
    }

    // ---- diagonal extraction via fixed-source shuffles ----
    float zr[8];
    zr[0] = __shfl_sync(0xffffffffu, r0.x, 0);
    zr[1] = __shfl_sync(0xffffffffu, r0.x, 9);
    zr[2] = __shfl_sync(0xffffffffu, r0.x, 27);
    zr[3] = __shfl_sync(0xffffffffu, r0.x, 18);
    zr[4] = __shfl_sync(0xffffffffu, r1.x, 31);
    zr[5] = __shfl_sync(0xffffffffu, r1.x, 22);
    zr[6] = __shfl_sync(0xffffffffu, r1.x, 4);
    zr[7] = __shfl_sync(0xffffffffu, r1.x, 13);

    // ---- Phase 7: per-head output partials (W2 already in registers) ----
    {
        float p0 = zr[0] * wa0.x + zr[1] * wa0.y + zr[2] * wa0.z + zr[3] * wa0.w
                 + zr[4] * wa1.x + zr[5] * wa1.y + zr[6] * wa1.z + zr[7] * wa1.w;
        float p1 = zr[0] * wb0.x + zr[1] * wb0.y + zr[2] * wb0.z + zr[3] * wb0.w
                 + zr[4] * wb1.x + zr[5] * wb1.y + zr[6] * wb1.z + zr[7] * wb1.w;
        s_part[w][l]      = p0;
        s_part[w][l + 32] = p1;
    }
    __syncthreads();

    // ---- Phase 8: cross-head reduction, write out row i ----
    if (t < DM) {
        float acc = bias;
#pragma unroll
        for (int hh = 0; hh < NH; hh++) acc += s_part[hh][t];
        out[i * DM + t] = acc;
    }
}

extern "C" void kernel_launch(void* const* d_in, const int* in_sizes, int n_in,
                              void* d_out, int out_size) {
    const float* x    = (const float*)d_in[0];
    const float* pqc  = (const float*)d_in[1];
    const float* W1   = (const float*)d_in[2];
    const float* b1   = (const float*)d_in[3];
    const float* W2   = (const float*)d_in[4];
    const float* b2   = (const float*)d_in[5];
    float* out = (float*)d_out;

    qfused<<<SEQ, 256>>>(x, pqc, W1, b1, W2, b2, out);
}

// round 17
// speedup vs baseline: 1.0566x; 1.0226x over previous
#include <cuda_runtime.h>
#include <math.h>

#define NH 8
#define SEQ 32
#define DK 8
#define DM 64
#define PI_F 3.14159265358979323846f
#define W_MUL 0.6324555320336759f  // sqrt(2/5)

#define XPAD 68          // padded x/W1 stage row (floats); rows 16B-aligned

// packed f32x2 helpers (sm_103a FFMA2 path — only reachable via PTX)
#define FMA2(d, a, b, c) \
    asm("fma.rn.f32x2 %0, %1, %2, %3;" : "=l"(d) : "l"(a), "l"(b), "l"(c))
#define PACK2(out, lo, hi) \
    asm("mov.b64 %0, {%1, %2};" : "=l"(out) : "f"(lo), "f"(hi))
#define UNPACK2(lo, hi, in) \
    asm("mov.b64 {%0, %1}, %2;" : "=f"(lo), "=f"(hi) : "l"(in))

__device__ __forceinline__ float2 cmul(float2 a, float2 b) {
    return make_float2(fmaf(a.x, b.x, -a.y * b.y), fmaf(a.x, b.y, a.y * b.x));
}
// a * conj(b)
__device__ __forceinline__ float2 cmulc(float2 a, float2 b) {
    return make_float2(fmaf(a.x, b.x, a.y * b.y), fmaf(a.y, b.x, -a.x * b.y));
}
__device__ __forceinline__ float2 cadd(float2 a, float2 b) {
    return make_float2(a.x + b.x, a.y + b.y);
}
// acc += a*b
__device__ __forceinline__ void cmac(float2& acc, float2 a, float2 b) {
    acc.x = fmaf(a.x, b.x, fmaf(-a.y, b.y, acc.x));
    acc.y = fmaf(a.x, b.y, fmaf( a.y, b.x, acc.y));
}

// flat-64 gather permutation: P(m) = r(m>>3)*8 + r(m&7), r(a)=a^(a>>1). order 4.
__device__ __forceinline__ int Pmap(int m) {
    int a = m >> 3, c = m & 7;
    int ra = (a ^ (a >> 1)) & 7;
    int rc = (c ^ (c >> 1)) & 7;
    return ra * 8 + rc;
}

__device__ __forceinline__ float2 shfl2(float2 v, int m) {
    return make_float2(__shfl_xor_sync(0xffffffffu, v.x, m),
                       __shfl_xor_sync(0xffffffffu, v.y, m));
}

// grid = 32 (block = sequence row i), block = 256 (warp w = head h)
__global__ void __launch_bounds__(256)
qfused(const float* __restrict__ x,     // (32,64)
       const float* __restrict__ pqc,   // (8,3,9)
       const float* __restrict__ W1,    // (8,64)
       const float* __restrict__ b1,    // (8,)
       const float* __restrict__ W2,    // (64,64)
       const float* __restrict__ b2,    // (64,)
       float* __restrict__ out)         // (1,32,64)
{
    const int i = blockIdx.x;        // sequence row
    const int t = threadIdx.x;       // 0..255
    const int w = t >> 5;            // warp = head
    const int l = t & 31;

    __shared__ float  s_xs [SEQ][XPAD];       // staged x
    __shared__ float  s_ws [DK][XPAD];        // staged W1
    __shared__ float  s_psi[SEQ][9];
    __shared__ float4 s_u2[NH][3];            // u2 SU(2) pairs: (a.x,a.y,b.x,b.y)
    __shared__ float4 s_M[NH][3];             // Ma, Mc, Mb: (M00, M11, Re01, Im01)
    __shared__ float2 s_V[NH][SEQ][4];        // per (head,j): v00,v01,v10,v11
    __shared__ float2 s_chi0[NH][8];
    __shared__ float  s_part[NH][65];

    // ---- Prefetch W2 rows + b2 (latency hidden under prep) ----
    float4 wa0, wa1, wb0, wb1;
    {
        const float4* w2a = (const float4*)(W2 + l * DM + w * DK);
        const float4* w2b = (const float4*)(W2 + (l + 32) * DM + w * DK);
        wa0 = w2a[0]; wa1 = w2a[1];
        wb0 = w2b[0]; wb1 = w2b[1];
    }
    float bias = (t < DM) ? b2[t] : 0.f;

    // ---- Phase 0: stage x/W1 + per-head SU(2) factors + sign-form M's ----
    {
        const float4* xs = (const float4*)x;
#pragma unroll
        for (int k = 0; k < 2; k++) {
            int q = t + 256 * k;          // 0..511
            int s = q >> 4, j = q & 15;
            *(float4*)&s_xs[s][4 * j] = xs[q];
        }
        if (t < 128) {
            int c = t >> 4, j = t & 15;
            *(float4*)&s_ws[c][4 * j] = ((const float4*)W1)[t];
        }
    }
    // only 6 lanes needed: {0,2,4} -> M (g,q)=(0,0),(0,2),(1,1); {6,7,8} -> u2 q=l-6
    if (l == 0 || l == 2 || l == 4 || (l >= 6 && l < 9)) {
        int g, q;
        if (l < 6) { g = (l == 4) ? 1 : 0; q = (l == 0) ? 0 : (l == 2) ? 2 : 1; }
        else       { g = 2; q = l - 6; }
        const float* ap = pqc + w * 27 + g * 9 + q * 3;
        float a0 = ap[0] * W_MUL, a1 = ap[1] * W_MUL, a2 = ap[2] * W_MUL;
        float sx, cx, sy, cy, sz, cz;
        __sincosf(0.5f * a0, &sx, &cx);
        __sincosf(0.5f * a1, &sy, &cy);
        __sincosf(0.5f * a2, &sz, &cz);
        float2 m00 = make_float2(cy * cx,   sy * sx);
        float2 m01 = make_float2(-sy * cx, -cy * sx);
        if (g == 2) {
            // u2 = diag(e0, conj(e0)) * M(m00, m01) = M(e0*m00, e0*m01)
            float2 e0 = make_float2(cz, -sz);
            float2 a2c = cmul(e0, m00);
            float2 b2c = cmul(e0, m01);
            s_u2[w][q] = make_float4(a2c.x, a2c.y, b2c.x, b2c.y);
        } else {
            // M = u^dagger Z u (Rz phases cancel row-wise)
            float2 m10 = make_float2(sy * cx,  -cy * sx);
            float2 m11 = make_float2(cy * cx,  -sy * sx);
            int idx = (l == 0) ? 0 : (l == 2) ? 1 : 2;
            float M00 = fmaf(m00.x, m00.x, m00.y * m00.y)
                      - fmaf(m10.x, m10.x, m10.y * m10.y);
            float M11 = fmaf(m01.x, m01.x, m01.y * m01.y)
                      - fmaf(m11.x, m11.x, m11.y * m11.y);
            float2 t1 = cmulc(m01, m00);
            float2 t2 = cmulc(m11, m10);
            s_M[w][idx] = make_float4(M00, M11, t1.x - t2.x, t1.y - t2.y);
        }
    }
    __syncthreads();

    // ---- Phase 1: xq + normalize fused, packed f32x2 dot product ----
    {
        const int c = t & 7;
        const int s = t >> 3;             // 0..31
        const ulonglong2* wr = (const ulonglong2*)&s_ws[c][0];
        const ulonglong2* xr = (const ulonglong2*)&s_xs[s][0];
        unsigned long long acc0, acc1;
        float bc = b1[c];
        PACK2(acc0, bc, 0.0f);
        PACK2(acc1, 0.0f, 0.0f);
#pragma unroll
        for (int j = 0; j < 8; j++) {
            ulonglong2 wv = wr[j];
            ulonglong2 xv = xr[j];
            FMA2(acc0, xv.x, wv.x, acc0);
            FMA2(acc1, xv.y, wv.y, acc1);
        }
        float u0f, u1f, u2f, u3f;
        UNPACK2(u0f, u1f, acc0);
        UNPACK2(u2f, u3f, acc1);
        float a = (u0f + u1f) + (u2f + u3f);
        float sq = a * a;
#pragma unroll
        for (int d = 1; d < 8; d <<= 1)
            sq += __shfl_xor_sync(0xffffffffu, sq, d);
        s_psi[s][c] = a * rsqrtf(sq);
    }
    __syncthreads();

    // ============ everything below is warp-local (head h = w) ============

    // ---- Phase 3: K_l and Q via Kronecker quadratic forms ----
    float ph;
    float psl[8];
    {
#pragma unroll
        for (int e = 0; e < 8; e++) psl[e] = s_psi[l][e];

        // K_l = psi_l^T (I (x) Mb (x) I) psi_l
        float4 Mb = s_M[w][2];
        float s0 = fmaf(psl[0], psl[0], fmaf(psl[1], psl[1],
                   fmaf(psl[4], psl[4], psl[5] * psl[5])));
        float s1 = fmaf(psl[2], psl[2], fmaf(psl[3], psl[3],
                   fmaf(psl[6], psl[6], psl[7] * psl[7])));
        float sx = fmaf(psl[0], psl[2], fmaf(psl[1], psl[3],
                   fmaf(psl[4], psl[6], psl[5] * psl[7])));
        float K = fmaf(Mb.x, s0, fmaf(Mb.y, s1, 2.f * Mb.z * sx));

        // Q = psi_i^T (Ma (x) I (x) Mc) psi_i
        float qv[8];
#pragma unroll
        for (int e = 0; e < 8; e++) qv[e] = s_psi[i][e];    // broadcast
        float S00 = fmaf(qv[0], qv[0], qv[2] * qv[2]);
        float S11 = fmaf(qv[1], qv[1], qv[3] * qv[3]);
        float S22 = fmaf(qv[4], qv[4], qv[6] * qv[6]);
        float S33 = fmaf(qv[5], qv[5], qv[7] * qv[7]);
        float S01 = fmaf(qv[0], qv[1], qv[2] * qv[3]);
        float S23 = fmaf(qv[4], qv[5], qv[6] * qv[7]);
        float S02 = fmaf(qv[0], qv[4], qv[2] * qv[6]);
        float S13 = fmaf(qv[1], qv[5], qv[3] * qv[7]);
        float S03 = fmaf(qv[0], qv[5], qv[2] * qv[7]);
        float S12 = fmaf(qv[1], qv[4], qv[3] * qv[6]);
        float4 Ma = s_M[w][0], Mc = s_M[w][1];
        float Q = Ma.x * fmaf(Mc.x, S00, Mc.y * S11)
                + Ma.y * fmaf(Mc.x, S22, Mc.y * S33)
                + 2.f * ( fmaf(Ma.x * Mc.z, S01, Ma.y * Mc.z * S23)
                        + fmaf(Ma.z * Mc.x, S02, Ma.z * Mc.y * S13)
                        + fmaf(Ma.z * Mc.z - Ma.w * Mc.w, S03,
                               (Ma.z * Mc.z + Ma.w * Mc.w) * S12) );

        ph = PI_F * Q * K;
    }

    // ---- Phase 5: chi_l via SU(2)-fused single butterfly ----
    // n0 + n1 = |chi|^2 = 1 (unitary, |psi| = 1) -> n1 = 1 - n0
    {
        float s4, c4;
        __sincosf(0.25f * ph, &s4, &c4);
        float cc2 = c4 * c4, ss2 = s4 * s4, cs2 = c4 * s4;
        float sh = 2.f * cs2;             // sin(ph/2)
        float ch = cc2 - ss2;             // cos(ph/2)
        float2 e0 = make_float2(ch, -sh);
        // uw in SU(2) form: (aw, bw)
        float2 aw = cmul(e0, make_float2(cc2,  ss2));
        float2 bw = cmul(e0, make_float2(-cs2, -cs2));

        // fused SU(2) factors f[q] = uw * u2[q]: only top row (af, bf)
        // af = aw*a2 - bw*conj(b2);  bf = aw*b2 + bw*conj(a2)
        float2 fa[3], fb[3];
#pragma unroll
        for (int q = 0; q < 3; q++) {
            float4 u = s_u2[w][q];
            float a2x = u.x, a2y = u.y, b2x = u.z, b2y = u.w;
            fa[q].x = fmaf(aw.x, a2x, fmaf(-aw.y, a2y, fmaf(-bw.x, b2x, -bw.y * b2y)));
            fa[q].y = fmaf(aw.x, a2y, fmaf( aw.y, a2x, fmaf(-bw.y, b2x,  bw.x * b2y)));
            fb[q].x = fmaf(aw.x, b2x, fmaf(-aw.y, b2y, fmaf( bw.x, a2x,  bw.y * a2y)));
            fb[q].y = fmaf(aw.x, b2y, fmaf( aw.y, b2x, fmaf( bw.y, a2x, -bw.x * a2y)));
        }

        // single butterfly, SU(2) sign-folded; stage 1 real input
        float2 v[8];
        {
            float2 a = fa[0], b = fb[0];
#pragma unroll
            for (int k = 0; k < 4; k++) {
                float pa = psl[k], pb = psl[k | 4];
                v[k]     = make_float2(fmaf(a.x, pa,  b.x * pb),
                                       fmaf(a.y, pa,  b.y * pb));
                v[k | 4] = make_float2(fmaf(a.x, pb, -b.x * pa),
                                       fmaf(b.y, pa, -a.y * pb));
            }
        }
#pragma unroll
        for (int q = 1; q < 3; q++) {
            int p = 2 - q;
            float2 a = fa[q], b = fb[q];
#pragma unroll
            for (int k = 0; k < 8; k++) {
                if ((k >> p) & 1) continue;
                int k1 = k | (1 << p);
                float2 v0 = v[k], v1 = v[k1];
                // new0 = a*v0 + b*v1
                float2 n0v;
                n0v.x = fmaf(a.x, v0.x, fmaf(-a.y, v0.y, fmaf(b.x, v1.x, -b.y * v1.y)));
                n0v.y = fmaf(a.x, v0.y, fmaf( a.y, v0.x, fmaf(b.x, v1.y,  b.y * v1.x)));
                // new1 = -conj(b)*v0 + conj(a)*v1
                float2 n1v;
                n1v.x = fmaf(a.x, v1.x, fmaf( a.y, v1.y, fmaf(-b.x, v0.x, -b.y * v0.y)));
                n1v.y = fmaf(a.x, v1.y, fmaf(-a.y, v1.x, fmaf(-b.x, v0.y,  b.y * v0.x)));
                v[k] = n0v; v[k1] = n1v;
            }
        }

        float n0 = fmaf(v[0].x, v[0].x, v[0].y * v[0].y)
                 + fmaf(v[3].x, v[3].x, v[3].y * v[3].y)
                 + fmaf(v[5].x, v[5].x, v[5].y * v[5].y)
                 + fmaf(v[6].x, v[6].x, v[6].y * v[6].y);
        float n1 = 1.0f - n0;             // unitarity
        float2 V01 = make_float2(0.f, 0.f);
        V01 = cadd(V01, cmulc(v[0], v[4]));
        V01 = cadd(V01, cmulc(v[3], v[7]));
        V01 = cadd(V01, cmulc(v[5], v[1]));
        V01 = cadd(V01, cmulc(v[6], v[2]));
        s_V[w][l][0] = make_float2(n0, 0.f);
        s_V[w][l][1] = V01;
        s_V[w][l][2] = make_float2(n1, 0.f);
        s_V[w][l][3] = make_float2(V01.x, -V01.y);   // V11 = conj(V01)
        if (l == 0) {
#pragma unroll
            for (int e = 0; e < 8; e++) s_chi0[w][e] = v[e];
        }
    }
    __syncwarp();

    // ---- Phase 6: drifting-coordinate register scan ----
    // slot0 sel table only; slot1 sel = slot0 sel ^ {0,3,3,0}[k]
    int selA0[4];
    {
        int m = l;
        int p1 = Pmap(m), p2 = Pmap(p1), p3 = Pmap(p2);
        selA0[0] = (((m  >> 3) & 1) << 1) | ((((m  >> 3) ^ m ) & 1));
        selA0[1] = (((p3 >> 3) & 1) << 1) | ((((p3 >> 3) ^ p3) & 1));
        selA0[2] = (((p2 >> 3) & 1) << 1) | ((((p2 >> 3) ^ p2) & 1));
        selA0[3] = (((p1 >> 3) & 1) << 1) | ((((p1 >> 3) ^ p1) & 1));
    }
    const int dmarr[4] = {4, 22, 13, 31};

    float2 r0, r1;
    {
        float2 ca  = s_chi0[w][l >> 3];
        float2 ca1 = s_chi0[w][4 + (l >> 3)];
        float2 cc  = s_chi0[w][l & 7];
        r0 = cmulc(ca, cc);
        r1 = cmulc(ca1, cc);
    }

#pragma unroll
    for (int j = 1; j < SEQ; j++) {
        const int k = j & 3;
        const float2* vj = &s_V[w][j][0];

        float2 p0 = shfl2(r1, dmarr[k]);
        float2 p1 = shfl2(r0, dmarr[k]);

        float2 VA0 = vj[selA0[k]];
        float2 VB0 = vj[selA0[k] ^ 2];

        float2 n0 = cmul(r0, VA0); cmac(n0, p0, VB0);
        float2 n1;
        if (k == 0 || k == 3) {
            n1 = cmul(r1, VA0); cmac(n1, p1, VB0);
        } else {
            float2 VA1 = vj[selA0[k] ^ 3];
            float2 VB1 = vj[selA0[k] ^ 1];
            n1 = cmul(r1, VA1); cmac(n1, p1, VB1);
        }
        r0 = n0; r1 = n1;
    }

    // ---- diagonal extraction via fixed-source shuffles ----
    float zr[8];
    zr[0] = __shfl_sync(0xffffffffu, r0.x, 0);
    zr[1] = __shfl_sync(0xffffffffu, r0.x, 9);
    zr[2] = __shfl_sync(0xffffffffu, r0.x, 27);
    zr[3] = __shfl_sync(0xffffffffu, r0.x, 18);
    zr[4] = __shfl_sync(0xffffffffu, r1.x, 31);
    zr[5] = __shfl_sync(0xffffffffu, r1.x, 22);
    zr[6] = __shfl_sync(0xffffffffu, r1.x, 4);
    zr[7] = __shfl_sync(0xffffffffu, r1.x, 13);

    // ---- Phase 7: per-head output partials (W2 already in registers) ----
    {
        float p0 = zr[0] * wa0.x + zr[1] * wa0.y + zr[2] * wa0.z + zr[3] * wa0.w
                 + zr[4] * wa1.x + zr[5] * wa1.y + zr[6] * wa1.z + zr[7] * wa1.w;
        float p1 = zr[0] * wb0.x + zr[1] * wb0.y + zr[2] * wb0.z + zr[3] * wb0.w
                 + zr[4] * wb1.x + zr[5] * wb1.y + zr[6] * wb1.z + zr[7] * wb1.w;
        s_part[w][l]      = p0;
        s_part[w][l + 32] = p1;
    }
    __syncthreads();

    // ---- Phase 8: cross-head reduction, write out row i ----
    if (t < DM) {
        float acc = bias;
#pragma unroll
        for (int hh = 0; hh < NH; hh++) acc += s_part[hh][t];
        out[i * DM + t] = acc;
    }
}

extern "C" void kernel_launch(void* const* d_in, const int* in_sizes, int n_in,
                              void* d_out, int out_size) {
    const float* x    = (const float*)d_in[0];
    const float* pqc  = (const float*)d_in[1];
    const float* W1   = (const float*)d_in[2];
    const float* b1   = (const float*)d_in[3];
    const float* W2   = (const float*)d_in[4];
    const float* b2   = (const float*)d_in[5];
    float* out = (float*)d_out;

    qfused<<<SEQ, 256>>>(x, pqc, W1, b1, W2, b2, out);
}